// round 8
// baseline (speedup 1.0000x reference)
#include <cuda_runtime.h>
#include <math.h>

#define HID 512
#define QD 32
#define OFFN 496
#define NB 32
#define NT 512
#define NWARP 16

// ---------------- scratch (device globals) ----------------------------------
__device__ float d_h1[HID], d_h2[HID], d_u2[HID], d_g2[HID];
__device__ float d_h3[HID], d_u3[HID];          // u3 == w = M2 @ q_t
__device__ float d_y2[HID], d_y3[HID];          // y3 == y = M2 @ LTqt
__device__ float d_loff[OFFN], d_ldiag[QD], d_gvec[QD];
__device__ float d_zow[OFFN], d_zdw[QD];        // Wo@w, Wd@w
__device__ float d_zoy[OFFN], d_zdy[QD];        // Wo@y, Wd@y

// ---------------- flat grid barrier (R4/R7-proven) ---------------------------
__device__ unsigned int g_arrive = 0u;
__device__ volatile unsigned int g_gen = 0u;

__device__ __forceinline__ void grid_sync() {
    __syncthreads();
    __threadfence();
    if (threadIdx.x == 0) {
        unsigned int gen = g_gen;
        if (atomicAdd(&g_arrive, 1u) == NB - 1u) {
            g_arrive = 0u;
            __threadfence();
            g_gen = gen + 1u;
        } else {
            while (g_gen == gen) { }
        }
    }
    __syncthreads();
}

__device__ __forceinline__ void grid_arrive_only() {
    __syncthreads();
    __threadfence();
    if (threadIdx.x == 0) {
        unsigned int gen = g_gen;
        if (atomicAdd(&g_arrive, 1u) == NB - 1u) {
            g_arrive = 0u;
            __threadfence();
            g_gen = gen + 1u;
        }
    }
}

__device__ __forceinline__ float sigm(float x) { return 1.f / (1.f + expf(-x)); }

// warp dual-dot length-512: one W row (read-only) vs two smem RHS.
__device__ __forceinline__ void wdot512_dual(const float* __restrict__ W,
                                             const float* __restrict__ xa,
                                             const float* __restrict__ xb,
                                             int lane, float& ra, float& rb) {
    const float4* W4 = (const float4*)W;
    const float4* a4 = (const float4*)xa;
    const float4* b4 = (const float4*)xb;
    float sa = 0.f, sb = 0.f;
#pragma unroll
    for (int k = 0; k < 4; k++) {
        int i = lane + 32 * k;
        float4 wv = __ldg(W4 + i);
        float4 av = a4[i];
        float4 bv = b4[i];
        sa += wv.x * av.x + wv.y * av.y + wv.z * av.z + wv.w * av.w;
        sb += wv.x * bv.x + wv.y * bv.y + wv.z * bv.z + wv.w * bv.w;
    }
#pragma unroll
    for (int o = 16; o; o >>= 1) {
        sa += __shfl_xor_sync(0xffffffffu, sa, o);
        sb += __shfl_xor_sync(0xffffffffu, sb, o);
    }
    ra = sa; rb = sb;
}

// warp single dot length-512 vs smem RHS.
__device__ __forceinline__ float wdot512_s(const float* __restrict__ W,
                                           const float* __restrict__ xs, int lane) {
    const float4* W4 = (const float4*)W;
    const float4* x4 = (const float4*)xs;
    float acc = 0.f;
#pragma unroll
    for (int k = 0; k < 4; k++) {
        int i = lane + 32 * k;
        float4 wv = __ldg(W4 + i);
        float4 xv = x4[i];
        acc += wv.x * xv.x + wv.y * xv.y + wv.z * xv.z + wv.w * xv.w;
    }
#pragma unroll
    for (int o = 16; o; o >>= 1) acc += __shfl_xor_sync(0xffffffffu, acc, o);
    return acc;
}

// ---------------- the one kernel ---------------------------------------------
__global__ __launch_bounds__(NT)
void fused(const float* __restrict__ q, const float* __restrict__ q_t,
           const float* __restrict__ q_tt,
           const float* __restrict__ W1, const float* __restrict__ b1,
           const float* __restrict__ W2, const float* __restrict__ b2,
           const float* __restrict__ W3, const float* __restrict__ b3,
           const float* __restrict__ Wd, const float* __restrict__ bd,
           const float* __restrict__ Wo, const float* __restrict__ bo,
           const float* __restrict__ Wg1, const float* __restrict__ bg1,
           const float* __restrict__ Wg2, const float* __restrict__ bg2,
           const float* __restrict__ Wg3, const float* __restrict__ bg3,
           float* __restrict__ out) {
    __shared__ __align__(16) float shm[2304];
    int b = blockIdx.x, tid = threadIdx.x;
    int lane = tid & 31, w = tid >> 5;
    int wg = b * NWARP + w;                    // 0..511 global warp id

    // ======== Stage A ========================================================
    // blocks 0-15 : h1,u1 redundant (dual K=32 dots) -> h2,u2 (dual K=512)
    // blocks 16-31: g1 redundant -> g2
    if (b < 16) {
        float* sq  = shm;            // [32]
        float* sqt = shm + 32;       // [32]
        float* sH1 = shm + 64;       // [512]
        float* sU1 = shm + 576;      // [512]
        if (tid < QD) { sq[tid] = __ldg(q + tid); sqt[tid] = __ldg(q_t + tid); }
        __syncthreads();
        {
            const float4* w4 = (const float4*)(W1 + tid * QD);
            const float4* q4 = (const float4*)sq;
            const float4* t4 = (const float4*)sqt;
            float aq = __ldg(b1 + tid), at = 0.f;
#pragma unroll
            for (int k = 0; k < 8; k++) {
                float4 wv = __ldg(w4 + k);
                float4 qv = q4[k], tv = t4[k];
                aq += wv.x * qv.x + wv.y * qv.y + wv.z * qv.z + wv.w * qv.w;
                at += wv.x * tv.x + wv.y * tv.y + wv.z * tv.z + wv.w * tv.w;
            }
            float h = sigm(aq);
            sH1[tid] = h;
            sU1[tid] = h * (1.f - h) * at;
            if (b == 0) d_h1[tid] = h;
        }
        __syncthreads();
        int r0 = (b * NWARP + w) * 2;          // 2 rows per warp
#pragma unroll
        for (int i = 0; i < 2; i++) {
            int r = r0 + i;
            float dh, du;
            wdot512_dual(W2 + r * HID, sH1, sU1, lane, dh, du);
            if (lane == 0) {
                float h2 = sigm(dh + __ldg(b2 + r));
                d_h2[r] = h2;
                d_u2[r] = h2 * (1.f - h2) * du;
            }
        }
    } else {
        float* sq  = shm;            // [32]
        float* sG1 = shm + 32;       // [512]
        if (tid < QD) sq[tid] = __ldg(q + tid);
        __syncthreads();
        {
            const float4* w4 = (const float4*)(Wg1 + tid * QD);
            const float4* q4 = (const float4*)sq;
            float a = __ldg(bg1 + tid);
#pragma unroll
            for (int k = 0; k < 8; k++) {
                float4 wv = __ldg(w4 + k);
                float4 qv = q4[k];
                a += wv.x * qv.x + wv.y * qv.y + wv.z * qv.z + wv.w * qv.w;
            }
            sG1[tid] = sigm(a);
        }
        __syncthreads();
        int r0 = ((b - 16) * NWARP + w) * 2;
#pragma unroll
        for (int i = 0; i < 2; i++) {
            int r = r0 + i;
            float a = wdot512_s(Wg2 + r * HID, sG1, lane);
            if (lane == 0) d_g2[r] = sigm(a + __ldg(bg2 + r));
        }
    }
    grid_sync();

    // ======== Stage B: h3,u3 (dual) — 1 row per warp ========================
    {
        float* sH2 = shm;            // [512]
        float* sU2 = shm + 512;      // [512]
        sH2[tid] = d_h2[tid];
        sU2[tid] = d_u2[tid];
        __syncthreads();
        int r = wg;
        float dh, du;
        wdot512_dual(W3 + r * HID, sH2, sU2, lane, dh, du);
        if (lane == 0) {
            float h3 = sigm(dh + __ldg(b3 + r));
            d_h3[r] = h3;
            d_u3[r] = h3 * (1.f - h3) * du;
        }
    }
    grid_sync();

    // ======== Stage C: loff/zow, ldiag/zdw, gvec ============================
    {
        float* sH3 = shm;            // [512]
        float* sU3 = shm + 512;      // [512]
        float* sG2 = shm + 1024;     // [512]
        sH3[tid] = d_h3[tid];
        sU3[tid] = d_u3[tid];
        sG2[tid] = d_g2[tid];
        __syncthreads();
        for (int t = wg; t < OFFN + 2 * QD; t += 512) {
            if (t < OFFN) {
                float dh, du;
                wdot512_dual(Wo + t * HID, sH3, sU3, lane, dh, du);
                if (lane == 0) { d_loff[t] = dh + __ldg(bo + t); d_zow[t] = du; }
            } else if (t < OFFN + QD) {
                int i = t - OFFN;
                float dh, du;
                wdot512_dual(Wd + i * HID, sH3, sU3, lane, dh, du);
                if (lane == 0) { d_ldiag[i] = expf(dh + __ldg(bd + i)); d_zdw[i] = du; }
            } else {
                int i = t - OFFN - QD;
                float a = wdot512_s(Wg3 + i * HID, sG2, lane);
                if (lane == 0) d_gvec[i] = a + __ldg(bg3 + i);
            }
        }
    }
    grid_sync();

    // ======== Stage D: LTqt (redundant), y1 (redundant), y2 (1 row/warp) ====
    {
        float* sLo  = shm;           // [496]
        float* sLd  = shm + 496;     // [32]
        float* sqt  = shm + 528;     // [32]
        float* sLT  = shm + 560;     // [32]
        float* sH1v = shm + 592;     // [512]
        float* sY1  = shm + 1104;    // [512]
        if (tid < OFFN) sLo[tid] = d_loff[tid];
        if (tid < QD) { sLd[tid] = d_ldiag[tid]; sqt[tid] = __ldg(q_t + tid); }
        sH1v[tid] = d_h1[tid];
        __syncthreads();
        if (tid < QD) {
            int j = tid;
            float a = sLd[j] * sqt[j];
            for (int i = j + 1; i < QD; i++)
                a += sLo[((i * (i - 1)) >> 1) + j] * sqt[i];
            sLT[j] = a;
        }
        __syncthreads();
        {
            const float4* w4 = (const float4*)(W1 + tid * QD);
            const float4* l4 = (const float4*)sLT;
            float a = 0.f;
#pragma unroll
            for (int k = 0; k < 8; k++) {
                float4 wv = __ldg(w4 + k);
                float4 lv = l4[k];
                a += wv.x * lv.x + wv.y * lv.y + wv.z * lv.z + wv.w * lv.w;
            }
            float h = sH1v[tid];
            sY1[tid] = h * (1.f - h) * a;
        }
        __syncthreads();
        int r = wg;
        float a = wdot512_s(W2 + r * HID, sY1, lane);
        if (lane == 0) {
            float h2 = d_h2[r];
            d_y2[r] = h2 * (1.f - h2) * a;
        }
    }
    grid_sync();

    // ======== Stage E: y3 (1 row/warp) ======================================
    {
        float* sY2 = shm;            // [512]
        sY2[tid] = d_y2[tid];
        __syncthreads();
        int r = wg;
        float a = wdot512_s(W3 + r * HID, sY2, lane);
        if (lane == 0) {
            float h3 = d_h3[r];
            d_y3[r] = h3 * (1.f - h3) * a;
        }
    }
    grid_sync();

    // ======== Stage F: zoy, zdy =============================================
    {
        float* sY3 = shm;            // [512]
        sY3[tid] = d_y3[tid];
        __syncthreads();
        for (int t = wg; t < OFFN + QD; t += 512) {
            if (t < OFFN) {
                float a = wdot512_s(Wo + t * HID, sY3, lane);
                if (lane == 0) d_zoy[t] = a;
            } else {
                int i = t - OFFN;
                float a = wdot512_s(Wd + i * HID, sY3, lane);
                if (lane == 0) d_zdy[i] = a;
            }
        }
    }
    if (b != 0) {
        grid_arrive_only();
        return;
    }
    grid_sync();

    // ======== Final (block 0): tau = c1+c2 + 0.5*c3 - 0.5*c4 + g ============
    {
        float* sLo  = shm;          // [496]
        float* sLd  = shm + 496;    // [32]
        float* szow = shm + 528;    // [496]
        float* szoy = shm + 1024;   // [496]
        float* szdw = shm + 1520;   // [32]
        float* szdy = shm + 1552;   // [32]
        float* sqt  = shm + 1584;   // [32]
        float* sqtt = shm + 1616;   // [32]
        float* sgv  = shm + 1648;   // [32]
        float* sLT  = shm + 1680;   // [32]
        float* st   = shm + 1712;   // [32]
        for (int t = tid; t < OFFN; t += NT) {
            sLo[t] = d_loff[t]; szow[t] = d_zow[t]; szoy[t] = d_zoy[t];
        }
        if (tid < QD) {
            sLd[tid] = d_ldiag[tid]; szdw[tid] = d_zdw[tid]; szdy[tid] = d_zdy[tid];
            sqt[tid] = __ldg(q_t + tid); sqtt[tid] = __ldg(q_tt + tid);
            sgv[tid] = d_gvec[tid];
        }
        __syncthreads();
        if (tid < QD) {
            int j = tid;
            float lt = sLd[j] * sqt[j];
            float u1 = sLd[j] * sqtt[j];
            float s2 = sLd[j] * szdw[j] * sqt[j];
            for (int i = j + 1; i < QD; i++) {
                int p = ((i * (i - 1)) >> 1) + j;
                lt += sLo[p] * sqt[i];
                u1 += sLo[p] * sqtt[i];
                s2 += szow[p] * sqt[i];
            }
            sLT[j] = lt;
            st[j] = u1 + s2;
        }
        __syncthreads();
        if (tid < QD) {
            int i = tid;
            float c12 = sLd[i] * st[i];
            float c3  = sLd[i] * szdw[i] * sLT[i];
            float c4  = sqt[i] * sLd[i] * szdy[i];
            for (int j = 0; j < i; j++) {
                int p = ((i * (i - 1)) >> 1) + j;
                c12 += sLo[p] * st[j];
                c3  += szow[p] * sLT[j];
            }
            for (int k = i + 1; k < QD; k++) {
                int p = ((k * (k - 1)) >> 1) + i;
                c4 += sqt[k] * szoy[p];
            }
            out[i] = c12 + 0.5f * (c3 - c4) + sgv[i];
        }
    }
}

// ---------------- launch ------------------------------------------------------
extern "C" void kernel_launch(void* const* d_in, const int* in_sizes, int n_in,
                              void* d_out, int out_size) {
    const float* q    = (const float*)d_in[0];
    const float* q_t  = (const float*)d_in[1];
    const float* q_tt = (const float*)d_in[2];
    const float* W1   = (const float*)d_in[3];
    const float* b1   = (const float*)d_in[4];
    const float* W2   = (const float*)d_in[5];
    const float* b2   = (const float*)d_in[6];
    const float* W3   = (const float*)d_in[7];
    const float* b3   = (const float*)d_in[8];
    const float* Wd   = (const float*)d_in[9];
    const float* bd   = (const float*)d_in[10];
    const float* Wo   = (const float*)d_in[11];
    const float* bo   = (const float*)d_in[12];
    const float* Wg1  = (const float*)d_in[13];
    const float* bg1  = (const float*)d_in[14];
    const float* Wg2  = (const float*)d_in[15];
    const float* bg2  = (const float*)d_in[16];
    const float* Wg3  = (const float*)d_in[17];
    const float* bg3  = (const float*)d_in[18];
    float* out = (float*)d_out;

    fused<<<NB, NT>>>(q, q_t, q_tt, W1, b1, W2, b2, W3, b3, Wd, bd, Wo, bo,
                      Wg1, bg1, Wg2, bg2, Wg3, bg3, out);
}